// round 7
// baseline (speedup 1.0000x reference)
#include <cuda_runtime.h>
#include <cstdint>

// x [B=512, T=128, C=512] fp32; Wq/Wk/Wv [H=64, C=512]; out [B, T, 64] fp32.
// 512-thread CTA per batch (16 warps). mma.sync m16n8k8 tf32.
// 3-stage cp.async ring with ONE barrier per chunk; XOR-swizzled staging tiles.
#define TT 128
#define CC 512
#define HH 64
#define KT 32
#define NT_THREADS 512

#define PQK 132   // merged [Q|K] rows [128][128] tf32, pitch 132
#define PVT 132   // Vt [64][128] tf32
#define PS  132   // S/P [128][128]

// smem float offsets (all stage bases multiples of 32 floats)
#define OFF_QK  0
#define OFF_VT  (128 * PQK)                    // 16896
#define OFF_RING (OFF_VT + 64 * PVT)           // 25344
#define OFF_S   OFF_RING                       // S aliases ring (post-projection)
#define XBUF(st) (OFF_RING + (st) * 4096)              // 3 x 128*32
#define WBUF(st) (OFF_RING + 12288 + (st) * 6144)      // 3 x 192*32
#define SMEM_FLOATS (OFF_RING + 12288 + 3 * 6144)      // 56064 fl = 224256 B

__device__ __forceinline__ float tf32r(float f) {
    uint32_t u;
    asm("cvt.rna.tf32.f32 %0, %1;" : "=r"(u) : "f"(f));
    return __uint_as_float(u);
}
__device__ __forceinline__ uint32_t tf32b(float f) {
    uint32_t u;
    asm("cvt.rna.tf32.f32 %0, %1;" : "=r"(u) : "f"(f));
    return u;
}
__device__ __forceinline__ uint32_t fb(float f) { return __float_as_uint(f); }

__device__ __forceinline__ uint32_t smem_u32(const void* p) {
    uint32_t a;
    asm("{ .reg .u64 t; cvta.to.shared.u64 t, %1; cvt.u32.u64 %0, t; }" : "=r"(a) : "l"(p));
    return a;
}
__device__ __forceinline__ void cp16(uint32_t dst, const float* src) {
    asm volatile("cp.async.ca.shared.global [%0], [%1], 16;" :: "r"(dst), "l"(src));
}
#define CP_COMMIT() asm volatile("cp.async.commit_group;" ::: "memory")
#define CP_WAIT1()  asm volatile("cp.async.wait_group 1;"  ::: "memory")
#define CP_WAIT0()  asm volatile("cp.async.wait_group 0;"  ::: "memory")

__device__ __forceinline__ void mma8(float* d, const uint32_t* a, const uint32_t* b) {
    asm volatile(
        "mma.sync.aligned.m16n8k8.row.col.f32.tf32.tf32.f32 "
        "{%0,%1,%2,%3}, {%4,%5,%6,%7}, {%8,%9}, {%0,%1,%2,%3};"
        : "+f"(d[0]), "+f"(d[1]), "+f"(d[2]), "+f"(d[3])
        : "r"(a[0]), "r"(a[1]), "r"(a[2]), "r"(a[3]), "r"(b[0]), "r"(b[1]));
}

__global__ __launch_bounds__(NT_THREADS, 1)
void attn_hmma5_kernel(const float* __restrict__ x,
                       const float* __restrict__ Wq,
                       const float* __restrict__ Wk,
                       const float* __restrict__ Wv,
                       float* __restrict__ out)
{
    extern __shared__ float sm[];
    float* QKs = sm + OFF_QK;
    float* Vt  = sm + OFF_VT;
    float* Ss  = sm + OFF_S;
    const uint32_t sb = smem_u32(sm);

    const int tid  = threadIdx.x;
    const int wid  = tid >> 5;
    const int lane = tid & 31;
    const int l4   = lane >> 2;
    const int lk   = lane & 3;
    const int lks4 = lk ^ (l4 << 2);   // XOR-swizzle column key for staging tiles
    const int b    = blockIdx.x;
    const float* xb = x + (size_t)b * TT * CC;

    const int wr = wid >> 2;        // 0..3 : row-pair group (rows {wr, 7-wr})
    const int wc = wid & 3;         // 0..3 : column group
    const int rt0 = wr * 16;
    const int rt1 = (7 - wr) * 16;

    // --- cp.async tile stager: XOR-swizzled, no pitch padding ---
    auto issue_chunk = [&](int ch) {
        const int st = ch % 3;
        const int k0 = ch * KT;
        const uint32_t xB = sb + XBUF(st) * 4;
        const uint32_t wB = sb + WBUF(st) * 4;
#pragma unroll
        for (int q = 0; q < 2; q++) {            // X [128][32] = 1024 float4
            int idx = q * NT_THREADS + tid;
            int row = idx >> 3, c4 = idx & 7;
            uint32_t off = (uint32_t)(row * 32 + ((c4 << 2) ^ ((row & 7) << 2)));
            cp16(xB + off * 4, xb + row * CC + k0 + c4 * 4);
        }
#pragma unroll
        for (int q = 0; q < 3; q++) {            // W [192][32] = 1536 float4
            int idx = q * NT_THREADS + tid;
            int row = idx >> 3, c4 = idx & 7;
            const float* Wp = (row < 64) ? (Wq + row * CC)
                            : (row < 128) ? (Wk + (row - 64) * CC)
                                          : (Wv + (row - 128) * CC);
            uint32_t off = (uint32_t)(row * 32 + ((c4 << 2) ^ ((row & 7) << 2)));
            cp16(wB + off * 4, Wp + k0 + c4 * 4);
        }
        CP_COMMIT();
    };

    // ============ Phase 1: [Q|K|V] = x @ W^T (16 chunks, 3-stage ring) ============
    float acc[2][6][4];
#pragma unroll
    for (int i = 0; i < 2; i++)
#pragma unroll
        for (int j = 0; j < 6; j++)
#pragma unroll
            for (int k = 0; k < 4; k++) acc[i][j][k] = 0.0f;

    const int nb1 = wc * 48;

    issue_chunk(0);
    issue_chunk(1);

#pragma unroll 1
    for (int ch = 0; ch < 16; ch++) {
        if (ch == 15) { CP_WAIT0(); } else { CP_WAIT1(); }
        __syncthreads();                          // single barrier per chunk
        if (ch < 14) issue_chunk(ch + 2);         // writes stage (ch-1)%3: drained

        const int st = ch % 3;
        const float* Xs  = sm + XBUF(st);
        const float* Wsm = sm + WBUF(st);

#pragma unroll
        for (int ks = 0; ks < 4; ks++) {
            const int cA = (ks * 8) ^ lks4;
            const int cB = cA ^ 4;
            uint32_t a[2][4];
#pragma unroll
            for (int mt = 0; mt < 2; mt++) {
                const float* rp = Xs + ((mt ? rt1 : rt0) + l4) * 32;
                a[mt][0] = tf32b(rp[cA]);
                a[mt][1] = tf32b(rp[cA + 256]);   // +8 rows
                a[mt][2] = tf32b(rp[cB]);
                a[mt][3] = tf32b(rp[cB + 256]);
            }
#pragma unroll
            for (int nt = 0; nt < 6; nt++) {
                const float* rp = Wsm + (nb1 + nt * 8 + l4) * 32;
                uint32_t b2[2] = { tf32b(rp[cA]), tf32b(rp[cB]) };
                mma8(acc[0][nt], a[0], b2);
                mma8(acc[1][nt], a[1], b2);
            }
        }
    }

    // Epilogue: route D frags to QKs / Vt (tf32-rounded)
#pragma unroll
    for (int mt = 0; mt < 2; mt++) {
        const int r0 = (mt ? rt1 : rt0) + l4;
#pragma unroll
        for (int nt = 0; nt < 6; nt++) {
            const int c0 = nb1 + nt * 8 + 2 * lk;
            float d0 = tf32r(acc[mt][nt][0]), d1 = tf32r(acc[mt][nt][1]);
            float d2 = tf32r(acc[mt][nt][2]), d3 = tf32r(acc[mt][nt][3]);
            if (c0 < 128) {
                *reinterpret_cast<float2*>(QKs + r0 * PQK + c0)       = make_float2(d0, d1);
                *reinterpret_cast<float2*>(QKs + (r0 + 8) * PQK + c0) = make_float2(d2, d3);
            } else {
                const int h = c0 - 128;
                Vt[h * PVT + r0]           = d0;
                Vt[(h + 1) * PVT + r0]     = d1;
                Vt[h * PVT + r0 + 8]       = d2;
                Vt[(h + 1) * PVT + r0 + 8] = d3;
            }
        }
    }
    __syncthreads();

    // ============ Phase 2: S = Q K^T — balanced causal tiles ============
    {
        const int ntmax0 = 2 * wr + 1;
        const int ntmax1 = 15 - 2 * wr;
        float accS0[4][4], accS1[4][4];
#pragma unroll
        for (int j = 0; j < 4; j++)
#pragma unroll
            for (int k = 0; k < 4; k++) { accS0[j][k] = 0.0f; accS1[j][k] = 0.0f; }

#pragma unroll
        for (int ks = 0; ks < 8; ks++) {
            const int kk = ks * 8;
            uint32_t a0[4], a1[4];
            {
                const float* ap = QKs + (rt0 + l4) * PQK + kk + lk;
                a0[0] = fb(ap[0]); a0[1] = fb(ap[8 * PQK]);
                a0[2] = fb(ap[4]); a0[3] = fb(ap[8 * PQK + 4]);
            }
            {
                const float* ap = QKs + (rt1 + l4) * PQK + kk + lk;
                a1[0] = fb(ap[0]); a1[1] = fb(ap[8 * PQK]);
                a1[2] = fb(ap[4]); a1[3] = fb(ap[8 * PQK + 4]);
            }
#pragma unroll
            for (int u = 0; u < 4; u++) {
                const int nt = wc + 4 * u;
                if (nt <= ntmax1) {
                    const float* bp = QKs + (nt * 8 + l4) * PQK + 64 + kk + lk;
                    uint32_t b2[2] = { fb(bp[0]), fb(bp[4]) };
                    mma8(accS1[u], a1, b2);
                    if (nt <= ntmax0) mma8(accS0[u], a0, b2);
                }
            }
        }
#pragma unroll
        for (int u = 0; u < 4; u++) {
            const int nt = wc + 4 * u;
            const int c0 = nt * 8 + 2 * lk;
            if (nt <= ntmax1) {
                const int r0 = rt1 + l4;
                *reinterpret_cast<float2*>(Ss + r0 * PS + c0) =
                    make_float2(accS1[u][0], accS1[u][1]);
                *reinterpret_cast<float2*>(Ss + (r0 + 8) * PS + c0) =
                    make_float2(accS1[u][2], accS1[u][3]);
            }
            if (nt <= ntmax0) {
                const int r0 = rt0 + l4;
                *reinterpret_cast<float2*>(Ss + r0 * PS + c0) =
                    make_float2(accS0[u][0], accS0[u][1]);
                *reinterpret_cast<float2*>(Ss + (r0 + 8) * PS + c0) =
                    make_float2(accS0[u][2], accS0[u][3]);
            }
        }
    }
    __syncthreads();

    // ============ Softmax (scale + causal mask), P stored tf32, normalized ============
    {
        for (int rr = 0; rr < 8; rr++) {
            const int r = wid * 8 + rr;
            float v0 = Ss[r * PS + lane];
            float v1 = Ss[r * PS + lane + 32];
            float v2 = Ss[r * PS + lane + 64];
            float v3 = Ss[r * PS + lane + 96];
            v0 = (lane      <= r) ? v0 * 0.125f : -1e30f;
            v1 = (lane + 32 <= r) ? v1 * 0.125f : -1e30f;
            v2 = (lane + 64 <= r) ? v2 * 0.125f : -1e30f;
            v3 = (lane + 96 <= r) ? v3 * 0.125f : -1e30f;
            float m = fmaxf(fmaxf(v0, v1), fmaxf(v2, v3));
#pragma unroll
            for (int o = 16; o > 0; o >>= 1)
                m = fmaxf(m, __shfl_xor_sync(0xffffffffu, m, o));
            float e0 = __expf(v0 - m), e1 = __expf(v1 - m);
            float e2 = __expf(v2 - m), e3 = __expf(v3 - m);
            float s = e0 + e1 + e2 + e3;
#pragma unroll
            for (int o = 16; o > 0; o >>= 1)
                s += __shfl_xor_sync(0xffffffffu, s, o);
            const float inv = 1.0f / s;
            Ss[r * PS + lane]      = tf32r(e0 * inv);
            Ss[r * PS + lane + 32] = tf32r(e1 * inv);
            Ss[r * PS + lane + 64] = tf32r(e2 * inv);
            Ss[r * PS + lane + 96] = tf32r(e3 * inv);
        }
    }
    __syncthreads();

    // ============ Phase 3: O = P @ V — skip all-zero P k-tiles ============
    {
        const int nb3 = wc * 16;
        const int ksmax0 = 2 * wr + 1;
        const int ksmax1 = 15 - 2 * wr;
        float accO[2][2][4];
#pragma unroll
        for (int i = 0; i < 2; i++)
#pragma unroll
            for (int j = 0; j < 2; j++)
#pragma unroll
                for (int k = 0; k < 4; k++) accO[i][j][k] = 0.0f;

#pragma unroll
        for (int ks = 0; ks < 16; ks++) {
            if (ks <= ksmax1) {
                const int kk = ks * 8;
                uint32_t b2[2][2];
#pragma unroll
                for (int nt = 0; nt < 2; nt++) {
                    const float* bp = Vt + (nb3 + nt * 8 + l4) * PVT + kk + lk;
                    b2[nt][0] = fb(bp[0]); b2[nt][1] = fb(bp[4]);
                }
                uint32_t a1[4];
                {
                    const float* ap = Ss + (rt1 + l4) * PS + kk + lk;
                    a1[0] = fb(ap[0]); a1[1] = fb(ap[8 * PS]);
                    a1[2] = fb(ap[4]); a1[3] = fb(ap[8 * PS + 4]);
                }
                mma8(accO[1][0], a1, b2[0]);
                mma8(accO[1][1], a1, b2[1]);
                if (ks <= ksmax0) {
                    uint32_t a0[4];
                    const float* ap = Ss + (rt0 + l4) * PS + kk + lk;
                    a0[0] = fb(ap[0]); a0[1] = fb(ap[8 * PS]);
                    a0[2] = fb(ap[4]); a0[3] = fb(ap[8 * PS + 4]);
                    mma8(accO[0][0], a0, b2[0]);
                    mma8(accO[0][1], a0, b2[1]);
                }
            }
        }

#pragma unroll
        for (int mt = 0; mt < 2; mt++) {
            const int r0 = (mt ? rt1 : rt0) + l4;
#pragma unroll
            for (int nt = 0; nt < 2; nt++) {
                const int c0 = nb3 + nt * 8 + 2 * lk;
                *reinterpret_cast<float2*>(out + ((size_t)b * TT + r0) * HH + c0) =
                    make_float2(accO[mt][nt][0], accO[mt][nt][1]);
                *reinterpret_cast<float2*>(out + ((size_t)b * TT + r0 + 8) * HH + c0) =
                    make_float2(accO[mt][nt][2], accO[mt][nt][3]);
            }
        }
    }
}

extern "C" void kernel_launch(void* const* d_in, const int* in_sizes, int n_in,
                              void* d_out, int out_size)
{
    const float* x  = (const float*)d_in[0];
    const float* Wq = (const float*)d_in[1];
    const float* Wk = (const float*)d_in[2];
    const float* Wv = (const float*)d_in[3];
    float* out = (float*)d_out;

    const int B = in_sizes[0] / (TT * CC);                         // 512
    const size_t smem_bytes = (size_t)SMEM_FLOATS * sizeof(float); // 224256

    cudaFuncSetAttribute(attn_hmma5_kernel,
                         cudaFuncAttributeMaxDynamicSharedMemorySize,
                         (int)smem_bytes);
    attn_hmma5_kernel<<<B, NT_THREADS, smem_bytes>>>(x, Wq, Wk, Wv, out);
}

// round 8
// speedup vs baseline: 1.7280x; 1.7280x over previous
#include <cuda_runtime.h>
#include <cuda_fp16.h>
#include <cstdint>

// x [B=512, T=128, C=512] fp32; Wq/Wk/Wv [H=64, C=512]; out [B, T, 64] fp32.
// 256-thread CTA per batch. mma.sync m16n8k16 FP16 (same 10-bit mantissa as
// tf32, 2x rate). cp.async double-buffered fp32 staging; balanced causal split.
#define TT 128
#define CC 512
#define HH 64
#define KT 32

// pitches
#define PTF 40    // staging tiles, fp32 words  (float2 frag loads conflict-free)
#define PQH 72    // Qs/Ks [128][64] half       (72 halves = 36 words, 36%32=4)
#define PVH 136   // Vt [64][128] half          (68 words, 68%32=4)
#define PPH 136   // P  [128][128] half
#define PSF 132   // S  [128][128] fp32         (132%32=4)

// smem BYTE offsets
#define OFF_QS  0
#define OFF_KS  18432                       // 128*72*2
#define OFF_VT  36864                       // +128*72*2
#define OFF_SCR 54272                       // +64*136*2
#define OFF_S   OFF_SCR                     // fp32 S   (128*132*4 = 67584)
#define OFF_P   (OFF_SCR + 67584)           // half P   (128*136*2 = 34816)
#define XBUF(bf) (OFF_SCR + (bf) * 20480)               // 2 x 128*40*4
#define WBUF(bf) (OFF_SCR + 40960 + (bf) * 30720)       // 2 x 192*40*4
#define SMEM_BYTES (OFF_SCR + 40960 + 2 * 30720)        // 156672

__device__ __forceinline__ uint32_t packh(float lo, float hi) {
    __half2 h = __floats2half2_rn(lo, hi);
    return *reinterpret_cast<uint32_t*>(&h);
}
__device__ __forceinline__ uint32_t packh2(float2 v) { return packh(v.x, v.y); }

__device__ __forceinline__ uint32_t smem_u32(const void* p) {
    uint32_t a;
    asm("{ .reg .u64 t; cvta.to.shared.u64 t, %1; cvt.u32.u64 %0, t; }" : "=r"(a) : "l"(p));
    return a;
}
__device__ __forceinline__ void cp16(uint32_t dst, const float* src) {
    asm volatile("cp.async.ca.shared.global [%0], [%1], 16;" :: "r"(dst), "l"(src));
}
#define CP_COMMIT() asm volatile("cp.async.commit_group;" ::: "memory")
#define CP_WAIT1()  asm volatile("cp.async.wait_group 1;"  ::: "memory")
#define CP_WAIT0()  asm volatile("cp.async.wait_group 0;"  ::: "memory")

// D(f32) += A(f16 m16k16) * B(f16 k16n8)
__device__ __forceinline__ void mma16(float* d, const uint32_t* a, const uint32_t* b) {
    asm volatile(
        "mma.sync.aligned.m16n8k16.row.col.f32.f16.f16.f32 "
        "{%0,%1,%2,%3}, {%4,%5,%6,%7}, {%8,%9}, {%0,%1,%2,%3};"
        : "+f"(d[0]), "+f"(d[1]), "+f"(d[2]), "+f"(d[3])
        : "r"(a[0]), "r"(a[1]), "r"(a[2]), "r"(a[3]), "r"(b[0]), "r"(b[1]));
}

__global__ __launch_bounds__(256, 1)
void attn_fp16_kernel(const float* __restrict__ x,
                      const float* __restrict__ Wq,
                      const float* __restrict__ Wk,
                      const float* __restrict__ Wv,
                      float* __restrict__ out)
{
    extern __shared__ char smem[];
    __half* Qs = reinterpret_cast<__half*>(smem + OFF_QS);
    __half* Ks = reinterpret_cast<__half*>(smem + OFF_KS);
    __half* Vt = reinterpret_cast<__half*>(smem + OFF_VT);
    float*  Ss = reinterpret_cast<float*>(smem + OFF_S);
    __half* Ph = reinterpret_cast<__half*>(smem + OFF_P);
    const uint32_t* Qw = reinterpret_cast<const uint32_t*>(smem + OFF_QS);
    const uint32_t* Kw = reinterpret_cast<const uint32_t*>(smem + OFF_KS);
    const uint32_t* Vw = reinterpret_cast<const uint32_t*>(smem + OFF_VT);
    const uint32_t* Pw = reinterpret_cast<const uint32_t*>(smem + OFF_P);
    const uint32_t sb = smem_u32(smem);

    const int tid  = threadIdx.x;
    const int wid  = tid >> 5;
    const int lane = tid & 31;
    const int l4   = lane >> 2;
    const int lk   = lane & 3;
    const int b    = blockIdx.x;
    const float* xb = x + (size_t)b * TT * CC;

    const int wr = wid >> 1;        // 0..3
    const int wc = wid & 1;         // 0..1
    const int rt0 = wr * 16;        // row tiles {wr, 7-wr}
    const int rt1 = (7 - wr) * 16;

    // --- cp.async tile stagers (raw fp32, pitch 40) ---
    auto issue_chunk = [&](int ch, int bf) {
        const int k0 = ch * KT;
        const uint32_t xB = sb + XBUF(bf);
        const uint32_t wB = sb + WBUF(bf);
#pragma unroll
        for (int q = 0; q < 4; q++) {            // X [128][32] = 1024 float4
            int idx = q * 256 + tid;
            int row = idx >> 3, c4 = idx & 7;
            cp16(xB + (uint32_t)(row * PTF + c4 * 4) * 4, xb + row * CC + k0 + c4 * 4);
        }
#pragma unroll
        for (int q = 0; q < 6; q++) {            // W [192][32] = 1536 float4
            int idx = q * 256 + tid;
            int row = idx >> 3, c4 = idx & 7;
            const float* Wp = (row < 64) ? (Wq + row * CC)
                            : (row < 128) ? (Wk + (row - 64) * CC)
                                          : (Wv + (row - 128) * CC);
            cp16(wB + (uint32_t)(row * PTF + c4 * 4) * 4, Wp + k0 + c4 * 4);
        }
        CP_COMMIT();
    };

    // ============ Phase 1: [Q|K|V] = x @ W^T (16 chunks, double-buffered) ============
    float acc[2][12][4];
#pragma unroll
    for (int i = 0; i < 2; i++)
#pragma unroll
        for (int j = 0; j < 12; j++)
#pragma unroll
            for (int k = 0; k < 4; k++) acc[i][j][k] = 0.0f;

    const int nb1 = wc * 96;

    issue_chunk(0, 0);
    issue_chunk(1, 1);

#pragma unroll 1
    for (int ch = 0; ch < 16; ch++) {
        if (ch == 15) { CP_WAIT0(); } else { CP_WAIT1(); }
        __syncthreads();
        const int bf = ch & 1;
        const float* Xs  = reinterpret_cast<const float*>(smem + XBUF(bf));
        const float* Wsm = reinterpret_cast<const float*>(smem + WBUF(bf));

#pragma unroll
        for (int ks = 0; ks < 2; ks++) {         // 2 k16 steps per 32-chunk
            const int kk = ks * 16;
            uint32_t a[2][4];
#pragma unroll
            for (int mt = 0; mt < 2; mt++) {
                const float* ap = Xs + ((mt ? rt1 : rt0) + l4) * PTF + kk + 2 * lk;
                a[mt][0] = packh2(*reinterpret_cast<const float2*>(ap));
                a[mt][1] = packh2(*reinterpret_cast<const float2*>(ap + 8 * PTF));
                a[mt][2] = packh2(*reinterpret_cast<const float2*>(ap + 8));
                a[mt][3] = packh2(*reinterpret_cast<const float2*>(ap + 8 * PTF + 8));
            }
#pragma unroll
            for (int nt = 0; nt < 12; nt++) {
                const float* bp = Wsm + (nb1 + nt * 8 + l4) * PTF + kk + 2 * lk;
                uint32_t b2[2] = { packh2(*reinterpret_cast<const float2*>(bp)),
                                   packh2(*reinterpret_cast<const float2*>(bp + 8)) };
                mma16(acc[0][nt], a[0], b2);
                mma16(acc[1][nt], a[1], b2);
            }
        }
        __syncthreads();
        if (ch < 14) issue_chunk(ch + 2, ch & 1);
    }

    // Epilogue: route D frags to Qs / Ks (half, packed) and Vt (half, transposed)
#pragma unroll
    for (int mt = 0; mt < 2; mt++) {
        const int r0 = (mt ? rt1 : rt0) + l4;
#pragma unroll
        for (int nt = 0; nt < 12; nt++) {
            const int c0 = nb1 + nt * 8 + 2 * lk;
            if (c0 < 64) {
                *reinterpret_cast<uint32_t*>(Qs + r0 * PQH + c0) =
                    packh(acc[mt][nt][0], acc[mt][nt][1]);
                *reinterpret_cast<uint32_t*>(Qs + (r0 + 8) * PQH + c0) =
                    packh(acc[mt][nt][2], acc[mt][nt][3]);
            } else if (c0 < 128) {
                const int c = c0 - 64;
                *reinterpret_cast<uint32_t*>(Ks + r0 * PQH + c) =
                    packh(acc[mt][nt][0], acc[mt][nt][1]);
                *reinterpret_cast<uint32_t*>(Ks + (r0 + 8) * PQH + c) =
                    packh(acc[mt][nt][2], acc[mt][nt][3]);
            } else {
                const int h = c0 - 128;
                Vt[h * PVH + r0]           = __float2half_rn(acc[mt][nt][0]);
                Vt[(h + 1) * PVH + r0]     = __float2half_rn(acc[mt][nt][1]);
                Vt[h * PVH + r0 + 8]       = __float2half_rn(acc[mt][nt][2]);
                Vt[(h + 1) * PVH + r0 + 8] = __float2half_rn(acc[mt][nt][3]);
            }
        }
    }
    __syncthreads();

    // ============ Phase 2: S = Q K^T — balanced causal tiles (4 k16 steps) ============
    {
        const int ntmax0 = 2 * wr + 1;
        const int ntmax1 = 15 - 2 * wr;
        float accS0[8][4], accS1[8][4];
#pragma unroll
        for (int j = 0; j < 8; j++)
#pragma unroll
            for (int k = 0; k < 4; k++) { accS0[j][k] = 0.0f; accS1[j][k] = 0.0f; }

#pragma unroll
        for (int ks = 0; ks < 4; ks++) {
            const int kw = ks * 8 + lk;          // u32 offset within row (k16 step = 8 u32)
            uint32_t a0[4], a1[4];
            {
                const uint32_t* ap = Qw + (rt0 + l4) * 36 + kw;
                a0[0] = ap[0]; a0[1] = ap[36 * 8];
                a0[2] = ap[4]; a0[3] = ap[36 * 8 + 4];
            }
            {
                const uint32_t* ap = Qw + (rt1 + l4) * 36 + kw;
                a1[0] = ap[0]; a1[1] = ap[36 * 8];
                a1[2] = ap[4]; a1[3] = ap[36 * 8 + 4];
            }
#pragma unroll
            for (int u = 0; u < 8; u++) {
                const int nt = wc + 2 * u;
                if (nt <= ntmax1) {
                    const uint32_t* bp = Kw + (nt * 8 + l4) * 36 + kw;
                    uint32_t b2[2] = { bp[0], bp[4] };
                    mma16(accS1[u], a1, b2);
                    if (nt <= ntmax0) mma16(accS0[u], a0, b2);
                }
            }
        }
#pragma unroll
        for (int u = 0; u < 8; u++) {
            const int nt = wc + 2 * u;
            const int c0 = nt * 8 + 2 * lk;
            if (nt <= ntmax1) {
                const int r0 = rt1 + l4;
                *reinterpret_cast<float2*>(Ss + r0 * PSF + c0) =
                    make_float2(accS1[u][0], accS1[u][1]);
                *reinterpret_cast<float2*>(Ss + (r0 + 8) * PSF + c0) =
                    make_float2(accS1[u][2], accS1[u][3]);
            }
            if (nt <= ntmax0) {
                const int r0 = rt0 + l4;
                *reinterpret_cast<float2*>(Ss + r0 * PSF + c0) =
                    make_float2(accS0[u][0], accS0[u][1]);
                *reinterpret_cast<float2*>(Ss + (r0 + 8) * PSF + c0) =
                    make_float2(accS0[u][2], accS0[u][3]);
            }
        }
    }
    __syncthreads();

    // ============ Softmax (scale + causal mask); P -> half, normalized ============
    {
        for (int rr = 0; rr < 16; rr++) {
            const int r = wid * 16 + rr;
            float v0 = Ss[r * PSF + lane];
            float v1 = Ss[r * PSF + lane + 32];
            float v2 = Ss[r * PSF + lane + 64];
            float v3 = Ss[r * PSF + lane + 96];
            v0 = (lane      <= r) ? v0 * 0.125f : -1e30f;
            v1 = (lane + 32 <= r) ? v1 * 0.125f : -1e30f;
            v2 = (lane + 64 <= r) ? v2 * 0.125f : -1e30f;
            v3 = (lane + 96 <= r) ? v3 * 0.125f : -1e30f;
            float m = fmaxf(fmaxf(v0, v1), fmaxf(v2, v3));
#pragma unroll
            for (int o = 16; o > 0; o >>= 1)
                m = fmaxf(m, __shfl_xor_sync(0xffffffffu, m, o));
            float e0 = __expf(v0 - m), e1 = __expf(v1 - m);
            float e2 = __expf(v2 - m), e3 = __expf(v3 - m);
            float s = e0 + e1 + e2 + e3;
#pragma unroll
            for (int o = 16; o > 0; o >>= 1)
                s += __shfl_xor_sync(0xffffffffu, s, o);
            const float inv = 1.0f / s;
            Ph[r * PPH + lane]      = __float2half_rn(e0 * inv);
            Ph[r * PPH + lane + 32] = __float2half_rn(e1 * inv);
            Ph[r * PPH + lane + 64] = __float2half_rn(e2 * inv);
            Ph[r * PPH + lane + 96] = __float2half_rn(e3 * inv);
        }
    }
    __syncthreads();

    // ============ Phase 3: O = P @ V — 8 k16 steps, causal skip ============
    {
        const int nb3 = wc * 32;
        const int ksmax0 = wr;            // P rows rt0 zero beyond col 16*wr+15
        const int ksmax1 = 7 - wr;
        float accO[2][4][4];
#pragma unroll
        for (int i = 0; i < 2; i++)
#pragma unroll
            for (int j = 0; j < 4; j++)
#pragma unroll
                for (int k = 0; k < 4; k++) accO[i][j][k] = 0.0f;

#pragma unroll
        for (int ks = 0; ks < 8; ks++) {
            if (ks <= ksmax1) {
                const int kw = ks * 8 + lk;
                uint32_t b2[4][2];
#pragma unroll
                for (int nt = 0; nt < 4; nt++) {
                    const uint32_t* bp = Vw + (nb3 + nt * 8 + l4) * 68 + kw;
                    b2[nt][0] = bp[0]; b2[nt][1] = bp[4];
                }
                uint32_t a1[4];
                {
                    const uint32_t* ap = Pw + (rt1 + l4) * 68 + kw;
                    a1[0] = ap[0]; a1[1] = ap[68 * 8];
                    a1[2] = ap[4]; a1[3] = ap[68 * 8 + 4];
                }
#pragma unroll
                for (int nt = 0; nt < 4; nt++) mma16(accO[1][nt], a1, b2[nt]);
                if (ks <= ksmax0) {
                    uint32_t a0[4];
                    const uint32_t* ap = Pw + (rt0 + l4) * 68 + kw;
                    a0[0] = ap[0]; a0[1] = ap[68 * 8];
                    a0[2] = ap[4]; a0[3] = ap[68 * 8 + 4];
#pragma unroll
                    for (int nt = 0; nt < 4; nt++) mma16(accO[0][nt], a0, b2[nt]);
                }
            }
        }

#pragma unroll
        for (int mt = 0; mt < 2; mt++) {
            const int r0 = (mt ? rt1 : rt0) + l4;
#pragma unroll
            for (int nt = 0; nt < 4; nt++) {
                const int c0 = nb3 + nt * 8 + 2 * lk;
                *reinterpret_cast<float2*>(out + ((size_t)b * TT + r0) * HH + c0) =
                    make_float2(accO[mt][nt][0], accO[mt][nt][1]);
                *reinterpret_cast<float2*>(out + ((size_t)b * TT + r0 + 8) * HH + c0) =
                    make_float2(accO[mt][nt][2], accO[mt][nt][3]);
            }
        }
    }
}

extern "C" void kernel_launch(void* const* d_in, const int* in_sizes, int n_in,
                              void* d_out, int out_size)
{
    const float* x  = (const float*)d_in[0];
    const float* Wq = (const float*)d_in[1];
    const float* Wk = (const float*)d_in[2];
    const float* Wv = (const float*)d_in[3];
    float* out = (float*)d_out;

    const int B = in_sizes[0] / (TT * CC);   // 512

    cudaFuncSetAttribute(attn_fp16_kernel,
                         cudaFuncAttributeMaxDynamicSharedMemorySize, SMEM_BYTES);
    attn_fp16_kernel<<<B, 256, SMEM_BYTES>>>(x, Wq, Wk, Wv, out);
}